// round 12
// baseline (speedup 1.0000x reference)
#include <cuda_runtime.h>
#include <cuda_bf16.h>
#include <stdint.h>

#define TPB    512
#define VHASH  1024
#define NB     4096
#define BMW    4096          // bitmap words (V <= 131072)
#define NBR    256           // raw windowed buckets (width 1/32, window 8 l-units)
#define RAWCAP 768
#define PRCAP  1536
#define MAXB   256

// -------- global scratch (static __device__, allowed) --------
__device__ unsigned long long g_mass[MAXB * NB];   // per-row fixed-point mass hist (K0 rows)
__device__ float              g_sc[MAXB * 4];      // maxL, maxP, Sl, Sp

struct SMem {
    int hkey[VHASH];
    int hcnt[VHASH];
    unsigned bmp[BMW];
    unsigned rh[NBR];
    union {
        unsigned long long mass[NB];   // K3: smem copy of global hist
        unsigned fb[NB];               // K1 fallback: absolute raw-l hist
    } u;
    unsigned long long chunk[TPB];
    float rV[RAWCAP];  int rI[RAWCAP];
    float rVs[RAWCAP]; int rIs[RAWCAP];
    float pV[PRCAP];   int pI[PRCAP];
    float pVs[PRCAP];  int pIs[PRCAP];
    float w[PRCAP];
    float red[16];
    unsigned long long best;
    unsigned long long above;
    int nRaw, nPr, sres, nAlive, maxKept;
    float thresh;
};

// ---------------- helpers ----------------
__device__ __forceinline__ int bucketof(float x) {          // absolute domain
    float r = (x + 64.0f) * 32.0f;
    r = fminf(fmaxf(r, 0.0f), 4095.0f);
    return (int)r;
}

__device__ __forceinline__ unsigned fkey(float x) {
    unsigned b = __float_as_uint(x);
    return (b & 0x80000000u) ? ~b : (b | 0x80000000u);
}

__device__ __forceinline__ int hlook(const int* hkey, const int* hcnt, int v) {
    unsigned h = ((unsigned)v * 2654435761u) & (VHASH - 1);
    while (true) {
        int k = hkey[h];
        if (k == v) return hcnt[h];
        if (k < 0)  return 0;
        h = (h + 1) & (VHASH - 1);
    }
}

__device__ __forceinline__ float procval(float l, int c, float rp, float fp, float pp, float t) {
    float x = l;
    if (c > 0) {
        x = (x > 0.0f) ? __fdiv_rn(x, rp) : __fmul_rn(x, rp);
        x = __fsub_rn(__fsub_rn(x, __fmul_rn(__int2float_rn(c), fp)), pp);
    }
    return __fdiv_rn(x, t);
}

// JAX threefry2x32, key (0,42), partitionable; bits = out0 ^ out1
__device__ __forceinline__ unsigned threefry_bits_k42(unsigned lin) {
    unsigned x0 = 0u, x1 = lin;
    const unsigned k0 = 0u, k1 = 42u, k2 = 0x1BD11BF0u;
    x0 += k0; x1 += k1;
#define TFR(r) { x0 += x1; x1 = __funnelshift_l(x1, x1, r); x1 ^= x0; }
    TFR(13) TFR(15) TFR(26) TFR(6)
    x0 += k1; x1 += k2 + 1u;
    TFR(17) TFR(29) TFR(16) TFR(24)
    x0 += k2; x1 += k0 + 2u;
    TFR(13) TFR(15) TFR(26) TFR(6)
    x0 += k0; x1 += k1 + 3u;
    TFR(17) TFR(29) TFR(16) TFR(24)
    x0 += k1; x1 += k2 + 4u;
    TFR(13) TFR(15) TFR(26) TFR(6)
    x0 += k2; x1 += k0 + 5u;
#undef TFR
    return x0 ^ x1;
}

__device__ __forceinline__ float gumbel_of(unsigned lin_idx) {
    unsigned bits = threefry_bits_k42(lin_idx);
    float u = __uint_as_float((bits >> 9) | 0x3f800000u) - 1.0f;
    u = fmaxf(1e-10f, u + 1e-10f);
    return -logf(-logf(u));
}

__device__ float blockMaxF(float v, float* red) {
    for (int o = 16; o; o >>= 1) v = fmaxf(v, __shfl_xor_sync(0xffffffffu, v, o));
    int wp = threadIdx.x >> 5;
    if ((threadIdx.x & 31) == 0) red[wp] = v;
    __syncthreads();
    if (threadIdx.x < 32) {
        float x = (threadIdx.x < (TPB / 32)) ? red[threadIdx.x] : -INFINITY;
        for (int o = 8; o; o >>= 1) x = fmaxf(x, __shfl_xor_sync(0xffffffffu, x, o));
        if (threadIdx.x == 0) red[0] = x;
    }
    __syncthreads();
    float r = red[0];
    __syncthreads();
    return r;
}

__device__ float blockSumF(float v, float* red) {
    for (int o = 16; o; o >>= 1) v += __shfl_xor_sync(0xffffffffu, v, o);
    int wp = threadIdx.x >> 5;
    if ((threadIdx.x & 31) == 0) red[wp] = v;
    __syncthreads();
    if (threadIdx.x < 32) {
        float x = (threadIdx.x < (TPB / 32)) ? red[threadIdx.x] : 0.0f;
        for (int o = 8; o; o >>= 1) x += __shfl_xor_sync(0xffffffffu, x, o);
        if (threadIdx.x == 0) red[0] = x;
    }
    __syncthreads();
    float r = red[0];
    __syncthreads();
    return r;
}

// min bucket b with prefix count >= target; -1 if total < target
__device__ int prefixSearch(const unsigned* hist, int nb, unsigned target,
                            unsigned long long* chunk, int* sres) {
    int t = threadIdx.x;
    int per = (nb + TPB - 1) / TPB;
    int base = t * per;
    unsigned long long s = 0;
    for (int j = 0; j < per; j++) { int b = base + j; if (b < nb) s += hist[b]; }
    chunk[t] = s;
    __syncthreads();
    for (int off = 1; off < TPB; off <<= 1) {
        unsigned long long add = (t >= off) ? chunk[t - off] : 0ull;
        __syncthreads();
        chunk[t] += add;
        __syncthreads();
    }
    if (t == 0) *sres = nb + 1;
    __syncthreads();
    unsigned long long cum = (t > 0) ? chunk[t - 1] : 0ull;
    for (int j = 0; j < per; j++) {
        int b = base + j;
        if (b < nb) {
            cum += hist[b];
            if (cum >= target) { atomicMin(sres, b); break; }
        }
    }
    __syncthreads();
    int r = *sres;
    __syncthreads();
    return (r <= nb) ? r : -1;
}

// max bucket b with suffix count >= target; -1 if none (u32)
__device__ int suffixSearch32(const unsigned* hist, unsigned long long target,
                              unsigned long long* chunk, int* sres) {
    int t = threadIdx.x;
    int base = NB - 8 * (t + 1);
    unsigned long long s = 0;
#pragma unroll
    for (int j = 0; j < 8; j++) s += hist[base + j];
    chunk[t] = s;
    __syncthreads();
    for (int off = 1; off < TPB; off <<= 1) {
        unsigned long long add = (t >= off) ? chunk[t - off] : 0ull;
        __syncthreads();
        chunk[t] += add;
        __syncthreads();
    }
    if (t == 0) *sres = -1;
    __syncthreads();
    unsigned long long cum = (t > 0) ? chunk[t - 1] : 0ull;
    for (int j = 7; j >= 0; j--) {
        cum += hist[base + j];
        if (cum >= target) { atomicMax(sres, base + j); break; }
    }
    __syncthreads();
    int r = *sres;
    __syncthreads();
    return r;
}

__device__ int suffixSearch64(const unsigned long long* hist, unsigned long long target,
                              unsigned long long* chunk, int* sres) {
    int t = threadIdx.x;
    int base = NB - 8 * (t + 1);
    unsigned long long s = 0;
#pragma unroll
    for (int j = 0; j < 8; j++) s += hist[base + j];
    chunk[t] = s;
    __syncthreads();
    for (int off = 1; off < TPB; off <<= 1) {
        unsigned long long add = (t >= off) ? chunk[t - off] : 0ull;
        __syncthreads();
        chunk[t] += add;
        __syncthreads();
    }
    if (t == 0) *sres = -1;
    __syncthreads();
    unsigned long long cum = (t > 0) ? chunk[t - 1] : 0ull;
    for (int j = 7; j >= 0; j--) {
        cum += hist[base + j];
        if (cum >= target) { atomicMax(sres, base + j); break; }
    }
    __syncthreads();
    int r = *sres;
    __syncthreads();
    return r;
}

// stable descending rank sort (tie -> lower index first)
__device__ void ranksort(const float* v, const int* ix, int n, float* ov, int* oi) {
    for (int i = threadIdx.x; i < n; i += TPB) {
        float vi = v[i]; int ii = ix[i]; int r = 0;
        for (int j = 0; j < n; j++) {
            float vj = v[j];
            if (vj > vi || (vj == vi && ix[j] < ii)) r++;
        }
        ov[r] = vi; oi[r] = ii;
    }
}

// ================= K1: all rows; full sampling for K>0, stats for K0 =================
__global__ __launch_bounds__(TPB)
void samplerK1(
    const float* __restrict__ logits, const float* __restrict__ temp,
    const int*   __restrict__ topk,   const float* __restrict__ topp,
    const float* __restrict__ rep,    const float* __restrict__ freq,
    const float* __restrict__ pres,   const int*   __restrict__ outids,
    float* __restrict__ out, int B, int V, int L, int NL)
{
    extern __shared__ __align__(16) unsigned char smem_raw[];
    SMem* sm = reinterpret_cast<SMem*>(smem_raw);
    const int tid = threadIdx.x;
    const int row = blockIdx.x;
    const float* lrow = logits + (size_t)row * V;
    const float4* lrow4 = reinterpret_cast<const float4*>(lrow);
    const int V4 = V >> 2;
    const int Vt = V4 << 2;

    for (int i = tid; i < VHASH; i += TPB) { sm->hkey[i] = -1; sm->hcnt[i] = 0; }
    for (int i = tid; i < BMW;   i += TPB) sm->bmp[i] = 0u;
    for (int i = tid; i < NBR;   i += TPB) sm->rh[i] = 0u;
    if (tid == 0) { sm->nRaw = 0; sm->nPr = 0; sm->best = 0ull; }
    __syncthreads();

    const int* ids = outids + (size_t)row * L;
    for (int i = tid; i < L; i += TPB) {
        int v = ids[i];
        unsigned h = ((unsigned)v * 2654435761u) & (VHASH - 1);
        while (true) {
            int prev = atomicCAS(&sm->hkey[h], -1, v);
            if (prev == -1 || prev == v) { atomicAdd(&sm->hcnt[h], 1); break; }
            h = (h + 1) & (VHASH - 1);
        }
        atomicOr(&sm->bmp[(unsigned)v >> 5], 1u << ((unsigned)v & 31));
    }
    __syncthreads();

    const float T  = temp[row];
    const int   K  = topk[row];
    const float TP = topp[row];
    const float RP = rep[row], FP = freq[row], PP = pres[row];
    const bool  K0 = (K <= 0);
    const int   keff = K0 ? V : K;

    // ---- pass 1: maxes ----
    float ml = -INFINITY, mu = -INFINITY;
    if (!K0) {
#pragma unroll 4
        for (int i = tid; i < V4; i += TPB) {
            float4 v = lrow4[i];
            ml = fmaxf(ml, fmaxf(fmaxf(v.x, v.y), fmaxf(v.z, v.w)));
        }
        for (int idx = Vt + tid; idx < V; idx += TPB) ml = fmaxf(ml, lrow[idx]);
    } else {
#pragma unroll 2
        for (int i = tid; i < V4; i += TPB) {
            float4 v = lrow4[i];
            int base = i << 2;
            unsigned wb = sm->bmp[(unsigned)base >> 5] >> ((unsigned)base & 31);
            ml = fmaxf(ml, fmaxf(fmaxf(v.x, v.y), fmaxf(v.z, v.w)));
            if (!(wb & 1u)) mu = fmaxf(mu, v.x);
            if (!(wb & 2u)) mu = fmaxf(mu, v.y);
            if (!(wb & 4u)) mu = fmaxf(mu, v.z);
            if (!(wb & 8u)) mu = fmaxf(mu, v.w);
        }
        for (int idx = Vt + tid; idx < V; idx += TPB) {
            float l = lrow[idx];
            ml = fmaxf(ml, l);
            if (!((sm->bmp[(unsigned)idx >> 5] >> ((unsigned)idx & 31)) & 1u)) mu = fmaxf(mu, l);
        }
    }
    const float maxL = blockMaxF(ml, sm->red);
    float maxP = 0.0f;
    if (K0) {
        const float maxLu = blockMaxF(mu, sm->red);
        float smp = -INFINITY;
        for (int i = tid; i < L; i += TPB) {
            int v = ids[i];
            int c = hlook(sm->hkey, sm->hcnt, v);
            smp = fmaxf(smp, procval(lrow[v], c, RP, FP, PP, T));
        }
        const float seenMaxP = blockMaxF(smp, sm->red);
        maxP = fmaxf(__fdiv_rn(maxLu, T), seenMaxP);
        // zero global hist row
        unsigned long long* gm = g_mass + (size_t)row * NB;
        for (int i = tid; i < NB; i += TPB) gm[i] = 0ull;
    }
    __syncthreads();

    // ---- pass 2: sums + windowed raw hist ----
    float s0 = 0.f, s1 = 0.f, s2 = 0.f, s3 = 0.f, spl = 0.f;
    if (!K0) {
#pragma unroll 2
        for (int i = tid; i < V4; i += TPB) {
            float4 v = lrow4[i];
            s0 += __expf(v.x - maxL);
            s1 += __expf(v.y - maxL);
            s2 += __expf(v.z - maxL);
            s3 += __expf(v.w - maxL);
            float d0 = __fmul_rn(__fsub_rn(maxL, v.x), 32.0f);
            float d1 = __fmul_rn(__fsub_rn(maxL, v.y), 32.0f);
            float d2 = __fmul_rn(__fsub_rn(maxL, v.z), 32.0f);
            float d3 = __fmul_rn(__fsub_rn(maxL, v.w), 32.0f);
            if (d0 < 256.0f) atomicAdd(&sm->rh[(int)d0], 1u);
            if (d1 < 256.0f) atomicAdd(&sm->rh[(int)d1], 1u);
            if (d2 < 256.0f) atomicAdd(&sm->rh[(int)d2], 1u);
            if (d3 < 256.0f) atomicAdd(&sm->rh[(int)d3], 1u);
        }
        for (int idx = Vt + tid; idx < V; idx += TPB) {
            float l = lrow[idx];
            s0 += __expf(l - maxL);
            float d = __fmul_rn(__fsub_rn(maxL, l), 32.0f);
            if (d < 256.0f) atomicAdd(&sm->rh[(int)d], 1u);
        }
    } else {
#pragma unroll 2
        for (int i = tid; i < V4; i += TPB) {
            float4 v = lrow4[i];
            int base = i << 2;
            unsigned wb = sm->bmp[(unsigned)base >> 5] >> ((unsigned)base & 31);
            float lv[4] = {v.x, v.y, v.z, v.w};
#pragma unroll
            for (int j = 0; j < 4; j++) {
                float l = lv[j];
                s0 += __expf(l - maxL);
                float d = __fmul_rn(__fsub_rn(maxL, l), 32.0f);
                if (d < 256.0f) atomicAdd(&sm->rh[(int)d], 1u);
                int c = ((wb >> j) & 1u) ? hlook(sm->hkey, sm->hcnt, base + j) : 0;
                float p = procval(l, c, RP, FP, PP, T);
                spl += __expf(p - maxP);
            }
        }
        for (int idx = Vt + tid; idx < V; idx += TPB) {
            float l = lrow[idx];
            s0 += __expf(l - maxL);
            float d = __fmul_rn(__fsub_rn(maxL, l), 32.0f);
            if (d < 256.0f) atomicAdd(&sm->rh[(int)d], 1u);
            bool seen = (sm->bmp[(unsigned)idx >> 5] >> ((unsigned)idx & 31)) & 1u;
            int c = seen ? hlook(sm->hkey, sm->hcnt, idx) : 0;
            float p = procval(l, c, RP, FP, PP, T);
            spl += __expf(p - maxP);
        }
    }
    const float Sl = blockSumF((s0 + s1) + (s2 + s3), sm->red);
    float Sp = 0.0f;
    if (K0) {
        Sp = blockSumF(spl, sm->red);
        if (tid == 0) {
            g_sc[row * 4 + 0] = maxL;
            g_sc[row * 4 + 1] = maxP;
            g_sc[row * 4 + 2] = Sl;
            g_sc[row * 4 + 3] = Sp;
        }
    }

    // ---- thresholds ----
    int bR = prefixSearch(sm->rh, NBR, (unsigned)NL, sm->chunk, &sm->sres);
    int bP = -1;
    if (!K0) bP = prefixSearch(sm->rh, NBR, (unsigned)(keff + L), sm->chunk, &sm->sres);

    bool useAbs = false;
    int bRabs = -1, bPabs = -1;
    if (!K0 && (bR < 0 || bP < 0)) {
        useAbs = true;
        for (int i = tid; i < NB; i += TPB) sm->u.fb[i] = 0u;
        __syncthreads();
        for (int idx = tid; idx < V; idx += TPB)
            atomicAdd(&sm->u.fb[bucketof(lrow[idx])], 1u);
        __syncthreads();
        bRabs = suffixSearch32(sm->u.fb, (unsigned long long)NL, sm->chunk, &sm->sres);
        bPabs = suffixSearch32(sm->u.fb, (unsigned long long)(keff + L), sm->chunk, &sm->sres);
    }
    if (K0 && bR < 0) bR = NBR - 1;

    // ---- pass 3: collect candidates ----
    if (!K0) {
#pragma unroll 4
        for (int i = tid; i < V4; i += TPB) {
            float4 v = lrow4[i];
            int base = i << 2;
            float lv[4] = {v.x, v.y, v.z, v.w};
#pragma unroll
            for (int j = 0; j < 4; j++) {
                float l = lv[j];
                int idx = base + j;
                float d = __fmul_rn(__fsub_rn(maxL, l), 32.0f);
                bool tr = useAbs ? (bucketof(l) >= bRabs) : (d < 256.0f && (int)d <= bR);
                bool tp = useAbs ? (bucketof(l) >= bPabs) : (d < 256.0f && (int)d <= bP);
                if (tr) {
                    int s = atomicAdd(&sm->nRaw, 1);
                    if (s < RAWCAP) { sm->rV[s] = l; sm->rI[s] = idx; }
                }
                if (tp) {
                    bool seen = (sm->bmp[(unsigned)idx >> 5] >> ((unsigned)idx & 31)) & 1u;
                    if (!seen) {
                        int s = atomicAdd(&sm->nPr, 1);
                        if (s < PRCAP) { sm->pV[s] = __fdiv_rn(l, T); sm->pI[s] = idx; }
                    }
                }
            }
        }
        for (int idx = Vt + tid; idx < V; idx += TPB) {
            float l = lrow[idx];
            float d = __fmul_rn(__fsub_rn(maxL, l), 32.0f);
            bool tr = useAbs ? (bucketof(l) >= bRabs) : (d < 256.0f && (int)d <= bR);
            bool tp = useAbs ? (bucketof(l) >= bPabs) : (d < 256.0f && (int)d <= bP);
            if (tr) {
                int s = atomicAdd(&sm->nRaw, 1);
                if (s < RAWCAP) { sm->rV[s] = l; sm->rI[s] = idx; }
            }
            if (tp) {
                bool seen = (sm->bmp[(unsigned)idx >> 5] >> ((unsigned)idx & 31)) & 1u;
                if (!seen) {
                    int s = atomicAdd(&sm->nPr, 1);
                    if (s < PRCAP) { sm->pV[s] = __fdiv_rn(l, T); sm->pI[s] = idx; }
                }
            }
        }
        for (int h = tid; h < VHASH; h += TPB) {
            int k = sm->hkey[h];
            if (k >= 0) {
                float p = procval(lrow[k], sm->hcnt[h], RP, FP, PP, T);
                int s = atomicAdd(&sm->nPr, 1);
                if (s < PRCAP) { sm->pV[s] = p; sm->pI[s] = k; }
            }
        }
    } else {
        // K0: raw candidates only
#pragma unroll 4
        for (int i = tid; i < V4; i += TPB) {
            float4 v = lrow4[i];
            int base = i << 2;
            float lv[4] = {v.x, v.y, v.z, v.w};
#pragma unroll
            for (int j = 0; j < 4; j++) {
                float l = lv[j];
                float d = __fmul_rn(__fsub_rn(maxL, l), 32.0f);
                if (d < 256.0f && (int)d <= bR) {
                    int s = atomicAdd(&sm->nRaw, 1);
                    if (s < RAWCAP) { sm->rV[s] = l; sm->rI[s] = base + j; }
                }
            }
        }
        for (int idx = Vt + tid; idx < V; idx += TPB) {
            float l = lrow[idx];
            float d = __fmul_rn(__fsub_rn(maxL, l), 32.0f);
            if (d < 256.0f && (int)d <= bR) {
                int s = atomicAdd(&sm->nRaw, 1);
                if (s < RAWCAP) { sm->rV[s] = l; sm->rI[s] = idx; }
            }
        }
    }
    __syncthreads();
    const int nR = min(sm->nRaw, RAWCAP);
    const int nP = min(sm->nPr, PRCAP);
    __syncthreads();

    ranksort(sm->rV, sm->rI, nR, sm->rVs, sm->rIs);
    if (!K0) ranksort(sm->pV, sm->pI, nP, sm->pVs, sm->pIs);
    __syncthreads();

    if (!K0) {
        if (tid == 0) {
            float kth = sm->pVs[keff - 1];
            int na = keff;
            while (na < nP && sm->pVs[na] >= kth) na++;
            float m = sm->pVs[0];
            float Z = 0.0f;
            for (int i = 0; i < na; i++) Z += expf(sm->pVs[i] - m);
            float cum = 0.0f, th = sm->pVs[0];
            for (int i = 0; i < na; i++) {
                if (cum < TP) { th = sm->pVs[i]; cum += __fdiv_rn(expf(sm->pVs[i] - m), Z); }
                else break;
            }
            sm->thresh = th;
            sm->nAlive = na;
        }
        __syncthreads();
        const float th = sm->thresh;
        const int na = sm->nAlive;
        unsigned long long lbest = 0ull;
        for (int i = tid; i < na; i += TPB) {
            float v = sm->pVs[i];
            if (v < th) continue;
            int idx = sm->pIs[i];
            float score = v + gumbel_of((unsigned)(row * V + idx));
            unsigned long long key =
                ((unsigned long long)fkey(score) << 32) | (unsigned)(0xFFFFFFFFu - (unsigned)idx);
            lbest = max(lbest, key);
        }
        if (lbest) atomicMax(&sm->best, lbest);
        __syncthreads();
    }

    // ---- outputs ----
    const float logS = logf(Sl);
    const int NC = NL + 1;
    if (!K0 && tid == 0) {
        const int s = (int)(0xFFFFFFFFu - (unsigned)(sm->best & 0xFFFFFFFFull));
        float slp = (lrow[s] - maxL) - logS;
        out[row] = (float)s;
        out[B + row * NC] = slp;
        out[B + B * NC + row * NC] = (float)s;
    }
    for (int j = tid; j < NL && j < nR; j += TPB) {
        out[B + row * NC + 1 + j] = (sm->rVs[j] - maxL) - logS;
        out[B + B * NC + row * NC + 1 + j] = (float)sm->rIs[j];
    }
}

// ================= K2: K0 rows — sliced global mass histogram =================
#define K2T 256
__global__ __launch_bounds__(K2T)
void samplerK2(
    const float* __restrict__ logits, const float* __restrict__ temp,
    const int*   __restrict__ topk,
    const float* __restrict__ rep,    const float* __restrict__ freq,
    const float* __restrict__ pres,   const int*   __restrict__ outids,
    int V, int L)
{
    const int row = blockIdx.y;
    if (topk[row] > 0) return;
    __shared__ int hkey[VHASH];
    __shared__ int hcnt[VHASH];
    const int tid = threadIdx.x;
    for (int i = tid; i < VHASH; i += K2T) { hkey[i] = -1; hcnt[i] = 0; }
    __syncthreads();
    const int* ids = outids + (size_t)row * L;
    for (int i = tid; i < L; i += K2T) {
        int v = ids[i];
        unsigned h = ((unsigned)v * 2654435761u) & (VHASH - 1);
        while (true) {
            int prev = atomicCAS(&hkey[h], -1, v);
            if (prev == -1 || prev == v) { atomicAdd(&hcnt[h], 1); break; }
            h = (h + 1) & (VHASH - 1);
        }
    }
    __syncthreads();

    const float T  = temp[row];
    const float RP = rep[row], FP = freq[row], PP = pres[row];
    const float maxP = g_sc[row * 4 + 1];
    const float* lrow = logits + (size_t)row * V;
    unsigned long long* gm = g_mass + (size_t)row * NB;

    const int SLICE = (V + 31) / 32;
    const int lo = blockIdx.x * SLICE;
    const int hi = min(lo + SLICE, V);
    for (int idx = lo + tid; idx < hi; idx += K2T) {
        float l = lrow[idx];
        int c = hlook(hkey, hcnt, idx);
        float p = procval(l, c, RP, FP, PP, T);
        float ew = __expf(p - maxP);
        unsigned long long fx = (unsigned long long)((double)ew * 1099511627776.0); // 2^40
        if (fx) atomicAdd(&gm[bucketof(p)], fx);
    }
}

// ================= K3: K0 rows — threshold refine + gumbel sample =================
__global__ __launch_bounds__(TPB)
void samplerK3(
    const float* __restrict__ logits, const float* __restrict__ temp,
    const int*   __restrict__ topk,   const float* __restrict__ topp,
    const float* __restrict__ rep,    const float* __restrict__ freq,
    const float* __restrict__ pres,   const int*   __restrict__ outids,
    float* __restrict__ out, int B, int V, int L, int NL)
{
    const int row = blockIdx.x;
    if (topk[row] > 0) return;
    extern __shared__ __align__(16) unsigned char smem_raw[];
    SMem* sm = reinterpret_cast<SMem*>(smem_raw);
    const int tid = threadIdx.x;
    const float* lrow = logits + (size_t)row * V;

    for (int i = tid; i < VHASH; i += TPB) { sm->hkey[i] = -1; sm->hcnt[i] = 0; }
    for (int i = tid; i < BMW;   i += TPB) sm->bmp[i] = 0u;
    if (tid == 0) { sm->nPr = 0; sm->best = 0ull; sm->above = 0ull; sm->maxKept = -1; }
    __syncthreads();
    const int* ids = outids + (size_t)row * L;
    for (int i = tid; i < L; i += TPB) {
        int v = ids[i];
        unsigned h = ((unsigned)v * 2654435761u) & (VHASH - 1);
        while (true) {
            int prev = atomicCAS(&sm->hkey[h], -1, v);
            if (prev == -1 || prev == v) { atomicAdd(&sm->hcnt[h], 1); break; }
            h = (h + 1) & (VHASH - 1);
        }
        atomicOr(&sm->bmp[(unsigned)v >> 5], 1u << ((unsigned)v & 31));
    }
    // load hist
    const unsigned long long* gm = g_mass + (size_t)row * NB;
    for (int i = tid; i < NB; i += TPB) sm->u.mass[i] = gm[i];
    __syncthreads();

    const float T  = temp[row];
    const float TP = topp[row];
    const float RP = rep[row], FP = freq[row], PP = pres[row];
    const float maxL = g_sc[row * 4 + 0];
    const float maxP = g_sc[row * 4 + 1];
    const float Sl   = g_sc[row * 4 + 2];
    const float Sp   = g_sc[row * 4 + 3];

    const unsigned long long Pfix =
        (unsigned long long)((double)TP * (double)Sp * 1099511627776.0);
    const int bs = suffixSearch64(sm->u.mass, Pfix, sm->chunk, &sm->sres);

    if (bs >= 0) {
        unsigned long long la = 0ull;
        for (int i = bs + 2 + tid; i < NB; i += TPB) la += sm->u.mass[i];
        atomicAdd(&sm->above, la);
        __syncthreads();
        // collect boundary-bucket candidates
#pragma unroll 2
        for (int idx = tid; idx < V; idx += TPB) {
            float l = lrow[idx];
            bool seen = (sm->bmp[(unsigned)idx >> 5] >> ((unsigned)idx & 31)) & 1u;
            int c = seen ? hlook(sm->hkey, sm->hcnt, idx) : 0;
            float p = procval(l, c, RP, FP, PP, T);
            int bb = bucketof(p);
            if (bb == bs || bb == bs + 1) {
                int s = atomicAdd(&sm->nPr, 1);
                if (s < PRCAP) { sm->pV[s] = p; sm->pI[s] = idx; }
            }
        }
        __syncthreads();
        const int n = min(sm->nPr, PRCAP);
        const float A2 = (float)((double)sm->above * (1.0 / 1099511627776.0));
        __syncthreads();
        ranksort(sm->pV, sm->pI, n, sm->pVs, sm->pIs);
        __syncthreads();
        for (int i = tid; i < n; i += TPB) sm->w[i] = expf(sm->pVs[i] - maxP);
        __syncthreads();
        const float Pf = __fmul_rn(TP, Sp);
        int lk = -1;
        for (int i = tid; i < n; i += TPB) {
            float cb = A2;
            for (int j = 0; j < i; j++) cb += sm->w[j];
            if (cb < Pf) lk = max(lk, i);
        }
        if (lk >= 0) atomicMax(&sm->maxKept, lk);
        __syncthreads();
        if (tid == 0)
            sm->thresh = (sm->maxKept >= 0) ? sm->pVs[sm->maxKept]
                                            : (n > 0 ? sm->pVs[0] : -INFINITY);
        __syncthreads();
    } else {
        if (tid == 0) sm->thresh = -INFINITY;
        __syncthreads();
    }

    // final gumbel pass
    const float th = sm->thresh;
    unsigned long long lbest = 0ull;
#pragma unroll 2
    for (int idx = tid; idx < V; idx += TPB) {
        float l = lrow[idx];
        bool seen = (sm->bmp[(unsigned)idx >> 5] >> ((unsigned)idx & 31)) & 1u;
        int c = seen ? hlook(sm->hkey, sm->hcnt, idx) : 0;
        float p = procval(l, c, RP, FP, PP, T);
        if (p >= th) {
            float score = p + gumbel_of((unsigned)(row * V + idx));
            unsigned long long key =
                ((unsigned long long)fkey(score) << 32) | (unsigned)(0xFFFFFFFFu - (unsigned)idx);
            lbest = max(lbest, key);
        }
    }
    if (lbest) atomicMax(&sm->best, lbest);
    __syncthreads();

    if (tid == 0) {
        const int s = (int)(0xFFFFFFFFu - (unsigned)(sm->best & 0xFFFFFFFFull));
        const float logS = logf(Sl);
        const int NC = NL + 1;
        out[row] = (float)s;
        out[B + row * NC] = (lrow[s] - maxL) - logS;
        out[B + B * NC + row * NC] = (float)s;
    }
}

extern "C" void kernel_launch(void* const* d_in, const int* in_sizes, int n_in,
                              void* d_out, int out_size) {
    const float* logits = (const float*)d_in[0];
    const float* temp   = (const float*)d_in[1];
    const int*   topk   = (const int*)  d_in[2];
    const float* topp   = (const float*)d_in[3];
    const float* rep    = (const float*)d_in[4];
    const float* freq   = (const float*)d_in[5];
    const float* pres   = (const float*)d_in[6];
    const int*   ids    = (const int*)  d_in[7];

    const int B = in_sizes[1];
    const int V = in_sizes[0] / B;
    const int L = in_sizes[7] / B;
    int NL = (out_size / B - 3) / 2;
    if (NL <= 0) NL = 20;

    static int smem_set = 0;
    if (!smem_set) {
        cudaFuncSetAttribute(samplerK1, cudaFuncAttributeMaxDynamicSharedMemorySize,
                             (int)sizeof(SMem));
        cudaFuncSetAttribute(samplerK3, cudaFuncAttributeMaxDynamicSharedMemorySize,
                             (int)sizeof(SMem));
        smem_set = 1;
    }
    samplerK1<<<B, TPB, sizeof(SMem)>>>(logits, temp, topk, topp, rep, freq, pres, ids,
                                        (float*)d_out, B, V, L, NL);
    samplerK2<<<dim3(32, B), K2T>>>(logits, temp, topk, rep, freq, pres, ids, V, L);
    samplerK3<<<B, TPB, sizeof(SMem)>>>(logits, temp, topk, topp, rep, freq, pres, ids,
                                        (float*)d_out, B, V, L, NL);
}

// round 13
// speedup vs baseline: 1.3399x; 1.3399x over previous
#include <cuda_runtime.h>
#include <cuda_bf16.h>
#include <stdint.h>

#define TPB    512
#define VHASH  1024
#define NB     4096
#define BMW    4096          // bitmap words (V <= 131072)
#define NBR    256           // raw windowed buckets (width 1/32, window 8 l-units)
#define RAWCAP 768
#define PRCAP  1536
#define MAXB   256
#define NSLICE 32

// -------- global scratch (static __device__, allowed) --------
__device__ unsigned long long g_mass[MAXB * NB];   // per-row fixed-point mass hist (K0 rows)
__device__ float              g_sc[MAXB * 4];      // maxL, maxP, Sl, Sp
__device__ int                g_bs[MAXB];
__device__ unsigned long long g_above[MAXB];
__device__ float              g_thresh[MAXB];
__device__ int                g_cnt[MAXB];
__device__ unsigned long long g_best[MAXB];
__device__ int                g_done[MAXB];
__device__ float              g_candV[MAXB * PRCAP];
__device__ int                g_candI[MAXB * PRCAP];

struct SMem {
    int hkey[VHASH];
    int hcnt[VHASH];
    unsigned bmp[BMW];
    unsigned rh[NBR];
    union {
        unsigned long long mass[NB];   // K3a: smem copy of global hist
        unsigned fb[NB];               // K1 fallback: absolute raw-l hist
    } u;
    unsigned long long chunk[TPB];
    float rV[RAWCAP];  int rI[RAWCAP];
    float rVs[RAWCAP]; int rIs[RAWCAP];
    float pV[PRCAP];   int pI[PRCAP];
    float pVs[PRCAP];  int pIs[PRCAP];
    float w[PRCAP];
    float red[16];
    unsigned long long best;
    unsigned long long above;
    int nRaw, nPr, sres, nAlive, maxKept;
    float thresh;
};

// ---------------- helpers ----------------
__device__ __forceinline__ int bucketof(float x) {          // absolute domain
    float r = (x + 64.0f) * 32.0f;
    r = fminf(fmaxf(r, 0.0f), 4095.0f);
    return (int)r;
}

__device__ __forceinline__ unsigned fkey(float x) {
    unsigned b = __float_as_uint(x);
    return (b & 0x80000000u) ? ~b : (b | 0x80000000u);
}

__device__ __forceinline__ int hlook(const int* hkey, const int* hcnt, int v) {
    unsigned h = ((unsigned)v * 2654435761u) & (VHASH - 1);
    while (true) {
        int k = hkey[h];
        if (k == v) return hcnt[h];
        if (k < 0)  return 0;
        h = (h + 1) & (VHASH - 1);
    }
}

__device__ __forceinline__ float procval(float l, int c, float rp, float fp, float pp, float t) {
    float x = l;
    if (c > 0) {
        x = (x > 0.0f) ? __fdiv_rn(x, rp) : __fmul_rn(x, rp);
        x = __fsub_rn(__fsub_rn(x, __fmul_rn(__int2float_rn(c), fp)), pp);
    }
    return __fdiv_rn(x, t);
}

// JAX threefry2x32, key (0,42), partitionable; bits = out0 ^ out1
__device__ __forceinline__ unsigned threefry_bits_k42(unsigned lin) {
    unsigned x0 = 0u, x1 = lin;
    const unsigned k0 = 0u, k1 = 42u, k2 = 0x1BD11BF0u;
    x0 += k0; x1 += k1;
#define TFR(r) { x0 += x1; x1 = __funnelshift_l(x1, x1, r); x1 ^= x0; }
    TFR(13) TFR(15) TFR(26) TFR(6)
    x0 += k1; x1 += k2 + 1u;
    TFR(17) TFR(29) TFR(16) TFR(24)
    x0 += k2; x1 += k0 + 2u;
    TFR(13) TFR(15) TFR(26) TFR(6)
    x0 += k0; x1 += k1 + 3u;
    TFR(17) TFR(29) TFR(16) TFR(24)
    x0 += k1; x1 += k2 + 4u;
    TFR(13) TFR(15) TFR(26) TFR(6)
    x0 += k2; x1 += k0 + 5u;
#undef TFR
    return x0 ^ x1;
}

__device__ __forceinline__ float gumbel_of(unsigned lin_idx) {
    unsigned bits = threefry_bits_k42(lin_idx);
    float u = __uint_as_float((bits >> 9) | 0x3f800000u) - 1.0f;
    u = fmaxf(1e-10f, u + 1e-10f);
    return -logf(-logf(u));
}

__device__ float blockMaxF(float v, float* red) {
    for (int o = 16; o; o >>= 1) v = fmaxf(v, __shfl_xor_sync(0xffffffffu, v, o));
    int wp = threadIdx.x >> 5;
    if ((threadIdx.x & 31) == 0) red[wp] = v;
    __syncthreads();
    if (threadIdx.x < 32) {
        float x = (threadIdx.x < (TPB / 32)) ? red[threadIdx.x] : -INFINITY;
        for (int o = 8; o; o >>= 1) x = fmaxf(x, __shfl_xor_sync(0xffffffffu, x, o));
        if (threadIdx.x == 0) red[0] = x;
    }
    __syncthreads();
    float r = red[0];
    __syncthreads();
    return r;
}

__device__ float blockSumF(float v, float* red) {
    for (int o = 16; o; o >>= 1) v += __shfl_xor_sync(0xffffffffu, v, o);
    int wp = threadIdx.x >> 5;
    if ((threadIdx.x & 31) == 0) red[wp] = v;
    __syncthreads();
    if (threadIdx.x < 32) {
        float x = (threadIdx.x < (TPB / 32)) ? red[threadIdx.x] : 0.0f;
        for (int o = 8; o; o >>= 1) x += __shfl_xor_sync(0xffffffffu, x, o);
        if (threadIdx.x == 0) red[0] = x;
    }
    __syncthreads();
    float r = red[0];
    __syncthreads();
    return r;
}

// min bucket b with prefix count >= target; -1 if total < target
__device__ int prefixSearch(const unsigned* hist, int nb, unsigned target,
                            unsigned long long* chunk, int* sres) {
    int t = threadIdx.x;
    int per = (nb + TPB - 1) / TPB;
    int base = t * per;
    unsigned long long s = 0;
    for (int j = 0; j < per; j++) { int b = base + j; if (b < nb) s += hist[b]; }
    chunk[t] = s;
    __syncthreads();
    for (int off = 1; off < TPB; off <<= 1) {
        unsigned long long add = (t >= off) ? chunk[t - off] : 0ull;
        __syncthreads();
        chunk[t] += add;
        __syncthreads();
    }
    if (t == 0) *sres = nb + 1;
    __syncthreads();
    unsigned long long cum = (t > 0) ? chunk[t - 1] : 0ull;
    for (int j = 0; j < per; j++) {
        int b = base + j;
        if (b < nb) {
            cum += hist[b];
            if (cum >= target) { atomicMin(sres, b); break; }
        }
    }
    __syncthreads();
    int r = *sres;
    __syncthreads();
    return (r <= nb) ? r : -1;
}

// max bucket b with suffix count >= target; -1 if none (u32)
__device__ int suffixSearch32(const unsigned* hist, unsigned long long target,
                              unsigned long long* chunk, int* sres) {
    int t = threadIdx.x;
    int base = NB - 8 * (t + 1);
    unsigned long long s = 0;
#pragma unroll
    for (int j = 0; j < 8; j++) s += hist[base + j];
    chunk[t] = s;
    __syncthreads();
    for (int off = 1; off < TPB; off <<= 1) {
        unsigned long long add = (t >= off) ? chunk[t - off] : 0ull;
        __syncthreads();
        chunk[t] += add;
        __syncthreads();
    }
    if (t == 0) *sres = -1;
    __syncthreads();
    unsigned long long cum = (t > 0) ? chunk[t - 1] : 0ull;
    for (int j = 7; j >= 0; j--) {
        cum += hist[base + j];
        if (cum >= target) { atomicMax(sres, base + j); break; }
    }
    __syncthreads();
    int r = *sres;
    __syncthreads();
    return r;
}

__device__ int suffixSearch64(const unsigned long long* hist, unsigned long long target,
                              unsigned long long* chunk, int* sres) {
    int t = threadIdx.x;
    int base = NB - 8 * (t + 1);
    unsigned long long s = 0;
#pragma unroll
    for (int j = 0; j < 8; j++) s += hist[base + j];
    chunk[t] = s;
    __syncthreads();
    for (int off = 1; off < TPB; off <<= 1) {
        unsigned long long add = (t >= off) ? chunk[t - off] : 0ull;
        __syncthreads();
        chunk[t] += add;
        __syncthreads();
    }
    if (t == 0) *sres = -1;
    __syncthreads();
    unsigned long long cum = (t > 0) ? chunk[t - 1] : 0ull;
    for (int j = 7; j >= 0; j--) {
        cum += hist[base + j];
        if (cum >= target) { atomicMax(sres, base + j); break; }
    }
    __syncthreads();
    int r = *sres;
    __syncthreads();
    return r;
}

// stable descending rank sort (tie -> lower index first)
__device__ void ranksort(const float* v, const int* ix, int n, float* ov, int* oi) {
    for (int i = threadIdx.x; i < n; i += TPB) {
        float vi = v[i]; int ii = ix[i]; int r = 0;
        for (int j = 0; j < n; j++) {
            float vj = v[j];
            if (vj > vi || (vj == vi && ix[j] < ii)) r++;
        }
        ov[r] = vi; oi[r] = ii;
    }
}

// ================= K1: all rows; full sampling for K>0, stats for K0 =================
__global__ __launch_bounds__(TPB)
void samplerK1(
    const float* __restrict__ logits, const float* __restrict__ temp,
    const int*   __restrict__ topk,   const float* __restrict__ topp,
    const float* __restrict__ rep,    const float* __restrict__ freq,
    const float* __restrict__ pres,   const int*   __restrict__ outids,
    float* __restrict__ out, int B, int V, int L, int NL)
{
    extern __shared__ __align__(16) unsigned char smem_raw[];
    SMem* sm = reinterpret_cast<SMem*>(smem_raw);
    const int tid = threadIdx.x;
    const int row = blockIdx.x;
    const float* lrow = logits + (size_t)row * V;
    const float4* lrow4 = reinterpret_cast<const float4*>(lrow);
    const int V4 = V >> 2;
    const int Vt = V4 << 2;

    for (int i = tid; i < VHASH; i += TPB) { sm->hkey[i] = -1; sm->hcnt[i] = 0; }
    for (int i = tid; i < BMW;   i += TPB) sm->bmp[i] = 0u;
    for (int i = tid; i < NBR;   i += TPB) sm->rh[i] = 0u;
    if (tid == 0) { sm->nRaw = 0; sm->nPr = 0; sm->best = 0ull; }
    __syncthreads();

    const int* ids = outids + (size_t)row * L;
    for (int i = tid; i < L; i += TPB) {
        int v = ids[i];
        unsigned h = ((unsigned)v * 2654435761u) & (VHASH - 1);
        while (true) {
            int prev = atomicCAS(&sm->hkey[h], -1, v);
            if (prev == -1 || prev == v) { atomicAdd(&sm->hcnt[h], 1); break; }
            h = (h + 1) & (VHASH - 1);
        }
        atomicOr(&sm->bmp[(unsigned)v >> 5], 1u << ((unsigned)v & 31));
    }
    __syncthreads();

    const float T  = temp[row];
    const int   K  = topk[row];
    const float TP = topp[row];
    const float RP = rep[row], FP = freq[row], PP = pres[row];
    const bool  K0 = (K <= 0);
    const int   keff = K0 ? V : K;

    // ---- pass 1: maxes ----
    float ml = -INFINITY, mu = -INFINITY;
    if (!K0) {
#pragma unroll 4
        for (int i = tid; i < V4; i += TPB) {
            float4 v = lrow4[i];
            ml = fmaxf(ml, fmaxf(fmaxf(v.x, v.y), fmaxf(v.z, v.w)));
        }
        for (int idx = Vt + tid; idx < V; idx += TPB) ml = fmaxf(ml, lrow[idx]);
    } else {
#pragma unroll 2
        for (int i = tid; i < V4; i += TPB) {
            float4 v = lrow4[i];
            int base = i << 2;
            unsigned wb = sm->bmp[(unsigned)base >> 5] >> ((unsigned)base & 31);
            ml = fmaxf(ml, fmaxf(fmaxf(v.x, v.y), fmaxf(v.z, v.w)));
            if (!(wb & 1u)) mu = fmaxf(mu, v.x);
            if (!(wb & 2u)) mu = fmaxf(mu, v.y);
            if (!(wb & 4u)) mu = fmaxf(mu, v.z);
            if (!(wb & 8u)) mu = fmaxf(mu, v.w);
        }
        for (int idx = Vt + tid; idx < V; idx += TPB) {
            float l = lrow[idx];
            ml = fmaxf(ml, l);
            if (!((sm->bmp[(unsigned)idx >> 5] >> ((unsigned)idx & 31)) & 1u)) mu = fmaxf(mu, l);
        }
    }
    const float maxL = blockMaxF(ml, sm->red);
    float maxP = 0.0f;
    if (K0) {
        const float maxLu = blockMaxF(mu, sm->red);
        float smp = -INFINITY;
        for (int i = tid; i < L; i += TPB) {
            int v = ids[i];
            int c = hlook(sm->hkey, sm->hcnt, v);
            smp = fmaxf(smp, procval(lrow[v], c, RP, FP, PP, T));
        }
        const float seenMaxP = blockMaxF(smp, sm->red);
        maxP = fmaxf(__fdiv_rn(maxLu, T), seenMaxP);
        unsigned long long* gm = g_mass + (size_t)row * NB;
        for (int i = tid; i < NB; i += TPB) gm[i] = 0ull;
    }
    __syncthreads();

    // ---- pass 2: sums + windowed raw hist ----
    float s0 = 0.f, s1 = 0.f, s2 = 0.f, s3 = 0.f, spl = 0.f;
    if (!K0) {
#pragma unroll 4
        for (int i = tid; i < V4; i += TPB) {
            float4 v = lrow4[i];
            s0 += __expf(v.x - maxL);
            s1 += __expf(v.y - maxL);
            s2 += __expf(v.z - maxL);
            s3 += __expf(v.w - maxL);
            float d0 = __fmul_rn(__fsub_rn(maxL, v.x), 32.0f);
            float d1 = __fmul_rn(__fsub_rn(maxL, v.y), 32.0f);
            float d2 = __fmul_rn(__fsub_rn(maxL, v.z), 32.0f);
            float d3 = __fmul_rn(__fsub_rn(maxL, v.w), 32.0f);
            if (d0 < 256.0f) atomicAdd(&sm->rh[(int)d0], 1u);
            if (d1 < 256.0f) atomicAdd(&sm->rh[(int)d1], 1u);
            if (d2 < 256.0f) atomicAdd(&sm->rh[(int)d2], 1u);
            if (d3 < 256.0f) atomicAdd(&sm->rh[(int)d3], 1u);
        }
        for (int idx = Vt + tid; idx < V; idx += TPB) {
            float l = lrow[idx];
            s0 += __expf(l - maxL);
            float d = __fmul_rn(__fsub_rn(maxL, l), 32.0f);
            if (d < 256.0f) atomicAdd(&sm->rh[(int)d], 1u);
        }
    } else {
#pragma unroll 2
        for (int i = tid; i < V4; i += TPB) {
            float4 v = lrow4[i];
            int base = i << 2;
            unsigned wb = sm->bmp[(unsigned)base >> 5] >> ((unsigned)base & 31);
            float lv[4] = {v.x, v.y, v.z, v.w};
#pragma unroll
            for (int j = 0; j < 4; j++) {
                float l = lv[j];
                s0 += __expf(l - maxL);
                float d = __fmul_rn(__fsub_rn(maxL, l), 32.0f);
                if (d < 256.0f) atomicAdd(&sm->rh[(int)d], 1u);
                int c = ((wb >> j) & 1u) ? hlook(sm->hkey, sm->hcnt, base + j) : 0;
                float p = procval(l, c, RP, FP, PP, T);
                spl += __expf(p - maxP);
            }
        }
        for (int idx = Vt + tid; idx < V; idx += TPB) {
            float l = lrow[idx];
            s0 += __expf(l - maxL);
            float d = __fmul_rn(__fsub_rn(maxL, l), 32.0f);
            if (d < 256.0f) atomicAdd(&sm->rh[(int)d], 1u);
            bool seen = (sm->bmp[(unsigned)idx >> 5] >> ((unsigned)idx & 31)) & 1u;
            int c = seen ? hlook(sm->hkey, sm->hcnt, idx) : 0;
            float p = procval(l, c, RP, FP, PP, T);
            spl += __expf(p - maxP);
        }
    }
    const float Sl = blockSumF((s0 + s1) + (s2 + s3), sm->red);
    float Sp = 0.0f;
    if (K0) {
        Sp = blockSumF(spl, sm->red);
        if (tid == 0) {
            g_sc[row * 4 + 0] = maxL;
            g_sc[row * 4 + 1] = maxP;
            g_sc[row * 4 + 2] = Sl;
            g_sc[row * 4 + 3] = Sp;
        }
    }

    // ---- thresholds ----
    int bR = prefixSearch(sm->rh, NBR, (unsigned)NL, sm->chunk, &sm->sres);
    int bP = -1;
    if (!K0) bP = prefixSearch(sm->rh, NBR, (unsigned)(keff + L), sm->chunk, &sm->sres);

    bool useAbs = false;
    int bRabs = -1, bPabs = -1;
    if (!K0 && (bR < 0 || bP < 0)) {
        useAbs = true;
        for (int i = tid; i < NB; i += TPB) sm->u.fb[i] = 0u;
        __syncthreads();
        for (int idx = tid; idx < V; idx += TPB)
            atomicAdd(&sm->u.fb[bucketof(lrow[idx])], 1u);
        __syncthreads();
        bRabs = suffixSearch32(sm->u.fb, (unsigned long long)NL, sm->chunk, &sm->sres);
        bPabs = suffixSearch32(sm->u.fb, (unsigned long long)(keff + L), sm->chunk, &sm->sres);
    }
    if (K0 && bR < 0) bR = NBR - 1;

    // ---- pass 3: collect candidates ----
    if (!K0) {
#pragma unroll 4
        for (int i = tid; i < V4; i += TPB) {
            float4 v = lrow4[i];
            int base = i << 2;
            float lv[4] = {v.x, v.y, v.z, v.w};
#pragma unroll
            for (int j = 0; j < 4; j++) {
                float l = lv[j];
                int idx = base + j;
                float d = __fmul_rn(__fsub_rn(maxL, l), 32.0f);
                bool tr = useAbs ? (bucketof(l) >= bRabs) : (d < 256.0f && (int)d <= bR);
                bool tp = useAbs ? (bucketof(l) >= bPabs) : (d < 256.0f && (int)d <= bP);
                if (tr) {
                    int s = atomicAdd(&sm->nRaw, 1);
                    if (s < RAWCAP) { sm->rV[s] = l; sm->rI[s] = idx; }
                }
                if (tp) {
                    bool seen = (sm->bmp[(unsigned)idx >> 5] >> ((unsigned)idx & 31)) & 1u;
                    if (!seen) {
                        int s = atomicAdd(&sm->nPr, 1);
                        if (s < PRCAP) { sm->pV[s] = __fdiv_rn(l, T); sm->pI[s] = idx; }
                    }
                }
            }
        }
        for (int idx = Vt + tid; idx < V; idx += TPB) {
            float l = lrow[idx];
            float d = __fmul_rn(__fsub_rn(maxL, l), 32.0f);
            bool tr = useAbs ? (bucketof(l) >= bRabs) : (d < 256.0f && (int)d <= bR);
            bool tp = useAbs ? (bucketof(l) >= bPabs) : (d < 256.0f && (int)d <= bP);
            if (tr) {
                int s = atomicAdd(&sm->nRaw, 1);
                if (s < RAWCAP) { sm->rV[s] = l; sm->rI[s] = idx; }
            }
            if (tp) {
                bool seen = (sm->bmp[(unsigned)idx >> 5] >> ((unsigned)idx & 31)) & 1u;
                if (!seen) {
                    int s = atomicAdd(&sm->nPr, 1);
                    if (s < PRCAP) { sm->pV[s] = __fdiv_rn(l, T); sm->pI[s] = idx; }
                }
            }
        }
        for (int h = tid; h < VHASH; h += TPB) {
            int k = sm->hkey[h];
            if (k >= 0) {
                float p = procval(lrow[k], sm->hcnt[h], RP, FP, PP, T);
                int s = atomicAdd(&sm->nPr, 1);
                if (s < PRCAP) { sm->pV[s] = p; sm->pI[s] = k; }
            }
        }
    } else {
#pragma unroll 4
        for (int i = tid; i < V4; i += TPB) {
            float4 v = lrow4[i];
            int base = i << 2;
            float lv[4] = {v.x, v.y, v.z, v.w};
#pragma unroll
            for (int j = 0; j < 4; j++) {
                float l = lv[j];
                float d = __fmul_rn(__fsub_rn(maxL, l), 32.0f);
                if (d < 256.0f && (int)d <= bR) {
                    int s = atomicAdd(&sm->nRaw, 1);
                    if (s < RAWCAP) { sm->rV[s] = l; sm->rI[s] = base + j; }
                }
            }
        }
        for (int idx = Vt + tid; idx < V; idx += TPB) {
            float l = lrow[idx];
            float d = __fmul_rn(__fsub_rn(maxL, l), 32.0f);
            if (d < 256.0f && (int)d <= bR) {
                int s = atomicAdd(&sm->nRaw, 1);
                if (s < RAWCAP) { sm->rV[s] = l; sm->rI[s] = idx; }
            }
        }
    }
    __syncthreads();
    const int nR = min(sm->nRaw, RAWCAP);
    const int nP = min(sm->nPr, PRCAP);
    __syncthreads();

    ranksort(sm->rV, sm->rI, nR, sm->rVs, sm->rIs);
    if (!K0) ranksort(sm->pV, sm->pI, nP, sm->pVs, sm->pIs);
    __syncthreads();

    if (!K0) {
        if (tid == 0) {
            float kth = sm->pVs[keff - 1];
            int na = keff;
            while (na < nP && sm->pVs[na] >= kth) na++;
            float m = sm->pVs[0];
            float Z = 0.0f;
            for (int i = 0; i < na; i++) Z += expf(sm->pVs[i] - m);
            float cum = 0.0f, th = sm->pVs[0];
            for (int i = 0; i < na; i++) {
                if (cum < TP) { th = sm->pVs[i]; cum += __fdiv_rn(expf(sm->pVs[i] - m), Z); }
                else break;
            }
            sm->thresh = th;
            sm->nAlive = na;
        }
        __syncthreads();
        const float th = sm->thresh;
        const int na = sm->nAlive;
        unsigned long long lbest = 0ull;
        for (int i = tid; i < na; i += TPB) {
            float v = sm->pVs[i];
            if (v < th) continue;
            int idx = sm->pIs[i];
            float score = v + gumbel_of((unsigned)(row * V + idx));
            unsigned long long key =
                ((unsigned long long)fkey(score) << 32) | (unsigned)(0xFFFFFFFFu - (unsigned)idx);
            lbest = max(lbest, key);
        }
        if (lbest) atomicMax(&sm->best, lbest);
        __syncthreads();
    }

    // ---- outputs ----
    const float logS = logf(Sl);
    const int NC = NL + 1;
    if (!K0 && tid == 0) {
        const int s = (int)(0xFFFFFFFFu - (unsigned)(sm->best & 0xFFFFFFFFull));
        float slp = (lrow[s] - maxL) - logS;
        out[row] = (float)s;
        out[B + row * NC] = slp;
        out[B + B * NC + row * NC] = (float)s;
    }
    for (int j = tid; j < NL && j < nR; j += TPB) {
        out[B + row * NC + 1 + j] = (sm->rVs[j] - maxL) - logS;
        out[B + B * NC + row * NC + 1 + j] = (float)sm->rIs[j];
    }
}

// ---- shared helper for sliced K0 kernels: build seen-token hash ----
#define K2T 256
__device__ void buildHash256(int* hkey, int* hcnt, const int* ids, int L) {
    const int tid = threadIdx.x;
    for (int i = tid; i < VHASH; i += K2T) { hkey[i] = -1; hcnt[i] = 0; }
    __syncthreads();
    for (int i = tid; i < L; i += K2T) {
        int v = ids[i];
        unsigned h = ((unsigned)v * 2654435761u) & (VHASH - 1);
        while (true) {
            int prev = atomicCAS(&hkey[h], -1, v);
            if (prev == -1 || prev == v) { atomicAdd(&hcnt[h], 1); break; }
            h = (h + 1) & (VHASH - 1);
        }
    }
    __syncthreads();
}

// ================= K2: K0 rows — sliced global mass histogram =================
__global__ __launch_bounds__(K2T)
void samplerK2(
    const float* __restrict__ logits, const float* __restrict__ temp,
    const int*   __restrict__ topk,
    const float* __restrict__ rep,    const float* __restrict__ freq,
    const float* __restrict__ pres,   const int*   __restrict__ outids,
    int V, int L)
{
    const int row = blockIdx.y;
    if (topk[row] > 0) return;
    __shared__ int hkey[VHASH];
    __shared__ int hcnt[VHASH];
    buildHash256(hkey, hcnt, outids + (size_t)row * L, L);

    const float T  = temp[row];
    const float RP = rep[row], FP = freq[row], PP = pres[row];
    const float maxP = g_sc[row * 4 + 1];
    const float* lrow = logits + (size_t)row * V;
    unsigned long long* gm = g_mass + (size_t)row * NB;

    const int SLICE = (V + NSLICE - 1) / NSLICE;
    const int lo = blockIdx.x * SLICE;
    const int hi = min(lo + SLICE, V);
    for (int idx = lo + threadIdx.x; idx < hi; idx += K2T) {
        float l = lrow[idx];
        int c = hlook(hkey, hcnt, idx);
        float p = procval(l, c, RP, FP, PP, T);
        float ew = __expf(p - maxP);
        unsigned long long fx = (unsigned long long)((double)ew * 1099511627776.0); // 2^40
        if (fx) atomicAdd(&gm[bucketof(p)], fx);
    }
}

// ================= K3a: K0 rows — suffix search on hist =================
__global__ __launch_bounds__(TPB)
void samplerK3a(const int* __restrict__ topk, const float* __restrict__ topp)
{
    const int row = blockIdx.x;
    if (topk[row] > 0) return;
    extern __shared__ __align__(16) unsigned char smem_raw[];
    SMem* sm = reinterpret_cast<SMem*>(smem_raw);
    const int tid = threadIdx.x;
    if (tid == 0) { sm->above = 0ull; }
    const unsigned long long* gm = g_mass + (size_t)row * NB;
    for (int i = tid; i < NB; i += TPB) sm->u.mass[i] = gm[i];
    __syncthreads();

    const float TP = topp[row];
    const float Sp = g_sc[row * 4 + 3];
    const unsigned long long Pfix =
        (unsigned long long)((double)TP * (double)Sp * 1099511627776.0);
    const int bs = suffixSearch64(sm->u.mass, Pfix, sm->chunk, &sm->sres);

    if (bs >= 0) {
        unsigned long long la = 0ull;
        for (int i = bs + 2 + tid; i < NB; i += TPB) la += sm->u.mass[i];
        atomicAdd(&sm->above, la);
    }
    __syncthreads();
    if (tid == 0) {
        g_bs[row] = bs;
        g_above[row] = sm->above;
        g_cnt[row] = 0;
    }
}

// ================= K3b: K0 rows — sliced boundary-bucket collect =================
__global__ __launch_bounds__(K2T)
void samplerK3b(
    const float* __restrict__ logits, const float* __restrict__ temp,
    const int*   __restrict__ topk,
    const float* __restrict__ rep,    const float* __restrict__ freq,
    const float* __restrict__ pres,   const int*   __restrict__ outids,
    int V, int L)
{
    const int row = blockIdx.y;
    if (topk[row] > 0) return;
    const int bs = g_bs[row];
    if (bs < 0) return;
    __shared__ int hkey[VHASH];
    __shared__ int hcnt[VHASH];
    buildHash256(hkey, hcnt, outids + (size_t)row * L, L);

    const float T  = temp[row];
    const float RP = rep[row], FP = freq[row], PP = pres[row];
    const float* lrow = logits + (size_t)row * V;

    const int SLICE = (V + NSLICE - 1) / NSLICE;
    const int lo = blockIdx.x * SLICE;
    const int hi = min(lo + SLICE, V);
    for (int idx = lo + threadIdx.x; idx < hi; idx += K2T) {
        float l = lrow[idx];
        int c = hlook(hkey, hcnt, idx);
        float p = procval(l, c, RP, FP, PP, T);
        int bb = bucketof(p);
        if (bb == bs || bb == bs + 1) {
            int s = atomicAdd(&g_cnt[row], 1);
            if (s < PRCAP) {
                g_candV[row * PRCAP + s] = p;
                g_candI[row * PRCAP + s] = idx;
            }
        }
    }
}

// ================= K3c: K0 rows — sort + exact threshold =================
__global__ __launch_bounds__(TPB)
void samplerK3c(const int* __restrict__ topk, const float* __restrict__ topp)
{
    const int row = blockIdx.x;
    if (topk[row] > 0) return;
    extern __shared__ __align__(16) unsigned char smem_raw[];
    SMem* sm = reinterpret_cast<SMem*>(smem_raw);
    const int tid = threadIdx.x;
    if (tid == 0) { sm->maxKept = -1; g_best[row] = 0ull; g_done[row] = 0; }
    const int bs = g_bs[row];
    if (bs < 0) {
        if (tid == 0) g_thresh[row] = -INFINITY;
        return;
    }
    const int n = min(g_cnt[row], PRCAP);
    for (int i = tid; i < n; i += TPB) {
        sm->pV[i] = g_candV[row * PRCAP + i];
        sm->pI[i] = g_candI[row * PRCAP + i];
    }
    __syncthreads();
    ranksort(sm->pV, sm->pI, n, sm->pVs, sm->pIs);
    __syncthreads();

    const float TP = topp[row];
    const float maxP = g_sc[row * 4 + 1];
    const float Sp   = g_sc[row * 4 + 3];
    const float A2 = (float)((double)g_above[row] * (1.0 / 1099511627776.0));
    for (int i = tid; i < n; i += TPB) sm->w[i] = expf(sm->pVs[i] - maxP);
    __syncthreads();
    const float Pf = __fmul_rn(TP, Sp);
    int lk = -1;
    for (int i = tid; i < n; i += TPB) {
        float cb = A2;
        for (int j = 0; j < i; j++) cb += sm->w[j];
        if (cb < Pf) lk = max(lk, i);
    }
    if (lk >= 0) atomicMax(&sm->maxKept, lk);
    __syncthreads();
    if (tid == 0)
        g_thresh[row] = (sm->maxKept >= 0) ? sm->pVs[sm->maxKept]
                                           : (n > 0 ? sm->pVs[0] : -INFINITY);
}

// ================= K3d: K0 rows — sliced final gumbel + output =================
__global__ __launch_bounds__(K2T)
void samplerK3d(
    const float* __restrict__ logits, const float* __restrict__ temp,
    const int*   __restrict__ topk,
    const float* __restrict__ rep,    const float* __restrict__ freq,
    const float* __restrict__ pres,   const int*   __restrict__ outids,
    float* __restrict__ out, int B, int V, int L, int NL)
{
    const int row = blockIdx.y;
    if (topk[row] > 0) return;
    __shared__ int hkey[VHASH];
    __shared__ int hcnt[VHASH];
    __shared__ unsigned long long sbest;
    if (threadIdx.x == 0) sbest = 0ull;
    buildHash256(hkey, hcnt, outids + (size_t)row * L, L);

    const float T  = temp[row];
    const float RP = rep[row], FP = freq[row], PP = pres[row];
    const float th = g_thresh[row];
    const float* lrow = logits + (size_t)row * V;

    const int SLICE = (V + NSLICE - 1) / NSLICE;
    const int lo = blockIdx.x * SLICE;
    const int hi = min(lo + SLICE, V);
    unsigned long long lbest = 0ull;
    for (int idx = lo + threadIdx.x; idx < hi; idx += K2T) {
        float l = lrow[idx];
        int c = hlook(hkey, hcnt, idx);
        float p = procval(l, c, RP, FP, PP, T);
        if (p >= th) {
            float score = p + gumbel_of((unsigned)(row * V + idx));
            unsigned long long key =
                ((unsigned long long)fkey(score) << 32) | (unsigned)(0xFFFFFFFFu - (unsigned)idx);
            lbest = max(lbest, key);
        }
    }
    if (lbest) atomicMax(&sbest, lbest);
    __syncthreads();
    if (threadIdx.x == 0) {
        if (sbest) atomicMax(&g_best[row], sbest);
        __threadfence();
        int d = atomicAdd(&g_done[row], 1);
        if (d == NSLICE - 1) {
            unsigned long long best = atomicAdd(&g_best[row], 0ull);
            const int s = (int)(0xFFFFFFFFu - (unsigned)(best & 0xFFFFFFFFull));
            const float maxL = g_sc[row * 4 + 0];
            const float Sl   = g_sc[row * 4 + 2];
            const float logS = logf(Sl);
            const int NC = NL + 1;
            out[row] = (float)s;
            out[B + row * NC] = (lrow[s] - maxL) - logS;
            out[B + B * NC + row * NC] = (float)s;
        }
    }
}

extern "C" void kernel_launch(void* const* d_in, const int* in_sizes, int n_in,
                              void* d_out, int out_size) {
    const float* logits = (const float*)d_in[0];
    const float* temp   = (const float*)d_in[1];
    const int*   topk   = (const int*)  d_in[2];
    const float* topp   = (const float*)d_in[3];
    const float* rep    = (const float*)d_in[4];
    const float* freq   = (const float*)d_in[5];
    const float* pres   = (const float*)d_in[6];
    const int*   ids    = (const int*)  d_in[7];

    const int B = in_sizes[1];
    const int V = in_sizes[0] / B;
    const int L = in_sizes[7] / B;
    int NL = (out_size / B - 3) / 2;
    if (NL <= 0) NL = 20;

    static int smem_set = 0;
    if (!smem_set) {
        cudaFuncSetAttribute(samplerK1,  cudaFuncAttributeMaxDynamicSharedMemorySize, (int)sizeof(SMem));
        cudaFuncSetAttribute(samplerK3a, cudaFuncAttributeMaxDynamicSharedMemorySize, (int)sizeof(SMem));
        cudaFuncSetAttribute(samplerK3c, cudaFuncAttributeMaxDynamicSharedMemorySize, (int)sizeof(SMem));
        smem_set = 1;
    }
    samplerK1<<<B, TPB, sizeof(SMem)>>>(logits, temp, topk, topp, rep, freq, pres, ids,
                                        (float*)d_out, B, V, L, NL);
    samplerK2<<<dim3(NSLICE, B), K2T>>>(logits, temp, topk, rep, freq, pres, ids, V, L);
    samplerK3a<<<B, TPB, sizeof(SMem)>>>(topk, topp);
    samplerK3b<<<dim3(NSLICE, B), K2T>>>(logits, temp, topk, rep, freq, pres, ids, V, L);
    samplerK3c<<<B, TPB, sizeof(SMem)>>>(topk, topp);
    samplerK3d<<<dim3(NSLICE, B), K2T>>>(logits, temp, topk, rep, freq, pres, ids,
                                         (float*)d_out, B, V, L, NL);
}